// round 7
// baseline (speedup 1.0000x reference)
#include <cuda_runtime.h>
#include <cstdint>
#include <math.h>

#define B_ 2
#define S_ 2048
#define H_ 32
#define KV_ 8
#define D_ 128
#define T_ (B_*S_)                 // 4096
#define HID_ (H_*D_)               // 4096
#define OUTQKV_ ((H_+2*KV_)*D_)    // 6144

// ---------------- scratch (device globals; no allocation allowed) ----------------
__device__ int8_t g_x8[(size_t)T_*HID_];          // 16 MB  packed q_hidden
__device__ int8_t g_wqkv8[(size_t)OUTQKV_*HID_];  // 25 MB  packed w_qkv
__device__ int8_t g_wo8[(size_t)HID_*HID_];       // 16 MB  packed w_o
__device__ float  g_qkv[(size_t)T_*OUTQKV_];      // 100 MB qkv projections (rope applied in place)
__device__ float  g_attn[(size_t)T_*HID_];        // 64 MB  attention output (pre-quant)
__device__ int8_t g_attnq[(size_t)T_*HID_];       // 16 MB  quantized attention
__device__ float  g_ascale[T_];

// ---------------- int32 -> int8 pack ----------------
__global__ void pack_int8_kernel(const int* __restrict__ in, int8_t* __restrict__ out, int n4) {
    int i = blockIdx.x * blockDim.x + threadIdx.x;
    if (i >= n4) return;
    int4 v = ((const int4*)in)[i];
    ((char4*)out)[i] = make_char4((signed char)v.x, (signed char)v.y,
                                  (signed char)v.z, (signed char)v.w);
}

// ---------------- block-scaled s8 GEMM: C[m,n] = rowscale[m] * sum_g colscale[n,g] * idot ----------------
__device__ __forceinline__ void mma_s8(int c[4], const int a[4], const int b[2]) {
    asm volatile(
        "mma.sync.aligned.m16n8k32.row.col.s32.s8.s8.s32 "
        "{%0,%1,%2,%3}, {%4,%5,%6,%7}, {%8,%9}, {%0,%1,%2,%3};\n"
        : "+r"(c[0]), "+r"(c[1]), "+r"(c[2]), "+r"(c[3])
        : "r"(a[0]), "r"(a[1]), "r"(a[2]), "r"(a[3]), "r"(b[0]), "r"(b[1]));
}

// A: [M,K] row-major int8.  Bm: [N,K] row-major int8 (i.e. B^T, K contiguous).
// colscale: [N, K/128].  rowscale: [M].  C: [M,N] fp32.
// Block 128x128, BK=128 (= one scale group). 256 threads = 8 warps (2 x 4), warp tile 64x32.
__global__ __launch_bounds__(256, 1) void gemm_s8_kernel(
    const int8_t* __restrict__ A, const int8_t* __restrict__ Bm,
    const float* __restrict__ colscale, const float* __restrict__ rowscale,
    float* __restrict__ C, int M, int N, int K)
{
    __shared__ int8_t smA[128 * 144];   // padded 144B rows -> conflict-free frag loads
    __shared__ int8_t smB[128 * 144];
    __shared__ float  sS[128];

    const int tid  = threadIdx.x;
    const int warp = tid >> 5, lane = tid & 31;
    const int wm = warp >> 2, wn = warp & 3;     // 2 x 4 warp grid
    const int g  = lane >> 2, tg = lane & 3;
    const int bm0 = blockIdx.y * 128, bn0 = blockIdx.x * 128;
    const int ng = K >> 7;

    float facc[4][4][4];
    #pragma unroll
    for (int mt = 0; mt < 4; ++mt)
        #pragma unroll
        for (int nt = 0; nt < 4; ++nt)
            #pragma unroll
            for (int e = 0; e < 4; ++e) facc[mt][nt][e] = 0.f;

    for (int grp = 0; grp < ng; ++grp) {
        __syncthreads();
        #pragma unroll
        for (int i = 0; i < 4; ++i) {
            int cidx = tid + i * 256;           // 1024 16B-chunks per tile
            int r = cidx >> 3, c = (cidx & 7) << 4;
            *(int4*)(smA + r * 144 + c) = *(const int4*)(A  + (size_t)(bm0 + r) * K + (grp << 7) + c);
            *(int4*)(smB + r * 144 + c) = *(const int4*)(Bm + (size_t)(bn0 + r) * K + (grp << 7) + c);
        }
        if (tid < 128) sS[tid] = colscale[(size_t)(bn0 + tid) * ng + grp];
        __syncthreads();

        int iacc[4][4][4];
        #pragma unroll
        for (int mt = 0; mt < 4; ++mt)
            #pragma unroll
            for (int nt = 0; nt < 4; ++nt)
                #pragma unroll
                for (int e = 0; e < 4; ++e) iacc[mt][nt][e] = 0;

        #pragma unroll
        for (int ks = 0; ks < 4; ++ks) {
            int a[4][4], b[4][2];
            #pragma unroll
            for (int mt = 0; mt < 4; ++mt) {
                const int8_t* p = smA + (wm * 64 + mt * 16 + g) * 144 + ks * 32 + tg * 4;
                a[mt][0] = *(const int*)(p);
                a[mt][1] = *(const int*)(p + 8 * 144);
                a[mt][2] = *(const int*)(p + 16);
                a[mt][3] = *(const int*)(p + 8 * 144 + 16);
            }
            #pragma unroll
            for (int nt = 0; nt < 4; ++nt) {
                const int8_t* p = smB + (wn * 32 + nt * 8 + g) * 144 + ks * 32 + tg * 4;
                b[nt][0] = *(const int*)(p);
                b[nt][1] = *(const int*)(p + 16);
            }
            #pragma unroll
            for (int mt = 0; mt < 4; ++mt)
                #pragma unroll
                for (int nt = 0; nt < 4; ++nt)
                    mma_s8(iacc[mt][nt], a[mt], b[nt]);
        }

        // fold exact int group sums into fp32 with per-column group scale
        #pragma unroll
        for (int mt = 0; mt < 4; ++mt)
            #pragma unroll
            for (int nt = 0; nt < 4; ++nt) {
                int colb = wn * 32 + nt * 8 + tg * 2;
                float s0 = sS[colb], s1 = sS[colb + 1];
                facc[mt][nt][0] += (float)iacc[mt][nt][0] * s0;
                facc[mt][nt][1] += (float)iacc[mt][nt][1] * s1;
                facc[mt][nt][2] += (float)iacc[mt][nt][2] * s0;
                facc[mt][nt][3] += (float)iacc[mt][nt][3] * s1;
            }
    }

    #pragma unroll
    for (int mt = 0; mt < 4; ++mt) {
        int r0 = bm0 + wm * 64 + mt * 16 + g;
        float rs0 = rowscale[r0], rs1 = rowscale[r0 + 8];
        #pragma unroll
        for (int nt = 0; nt < 4; ++nt) {
            int col = bn0 + wn * 32 + nt * 8 + tg * 2;
            *(float2*)(C + (size_t)r0 * N + col) =
                make_float2(facc[mt][nt][0] * rs0, facc[mt][nt][1] * rs0);
            *(float2*)(C + (size_t)(r0 + 8) * N + col) =
                make_float2(facc[mt][nt][2] * rs1, facc[mt][nt][3] * rs1);
        }
    }
}

// ---------------- RoPE (NeoX) in place on q and k sections of qkv ----------------
__global__ void rope_kernel(float* __restrict__ qkv) {
    int idx = blockIdx.x * 256 + threadIdx.x;
    if (idx >= T_ * (H_ + KV_) * 64) return;
    int i  = idx & 63;
    int hh = (idx >> 6) % (H_ + KV_);
    int t  = idx / ((H_ + KV_) * 64);
    int s  = t & (S_ - 1);
    int col = (hh < H_) ? hh * D_ : HID_ + (hh - H_) * D_;
    float e   = (float)i * (1.0f / 64.0f);
    float inv = 1.0f / powf(1.0e6f, e);
    float ang = (float)s * inv;
    float sn, c;
    sincosf(ang, &sn, &c);
    float* p = qkv + (size_t)t * OUTQKV_ + col;
    float x1 = p[i], x2 = p[i + 64];
    p[i]      = x1 * c - x2 * sn;
    p[i + 64] = x2 * c + x1 * sn;
}

// ---------------- fp32 causal flash attention (GQA 4:1), one thread = one query row ----------------
// grid (S/256, H, B), 256 threads. smem: q[256][132] (padded), k[64][128], v[64][128].
__global__ __launch_bounds__(256, 1) void attn_kernel(const float* __restrict__ qkv,
                                                      float* __restrict__ attn) {
    extern __shared__ float sm[];
    float* q_s = sm;                       // 256*132 floats
    float* k_s = sm + 256 * 132;           // 64*128
    float* v_s = k_s + 64 * 128;           // 64*128

    const int tid = threadIdx.x;
    const int qb = blockIdx.x, h = blockIdx.y, b = blockIdx.z;
    const int g = h >> 2;
    const float scale = 0.08838834764831845f;  // D^-0.5

    for (int idx = tid; idx < 256 * 32; idx += 256) {
        int r = idx >> 5, d4 = idx & 31;
        float4 v = *(const float4*)(qkv + (size_t)(b * S_ + qb * 256 + r) * OUTQKV_ + h * D_ + d4 * 4);
        v.x *= scale; v.y *= scale; v.z *= scale; v.w *= scale;
        *(float4*)(q_s + r * 132 + d4 * 4) = v;
    }
    __syncthreads();

    const int qpos = qb * 256 + tid;
    float o[128];
    #pragma unroll
    for (int d = 0; d < 128; ++d) o[d] = 0.f;
    float m = -1e30f, l = 0.f;
    const int nkb = (qb + 1) * 4;
    const float* qrow = q_s + tid * 132;

    for (int kb = 0; kb < nkb; ++kb) {
        __syncthreads();
        for (int idx = tid; idx < 64 * 32; idx += 256) {
            int r = idx >> 5, d4 = idx & 31;
            const float* base = qkv + (size_t)(b * S_ + kb * 64 + r) * OUTQKV_;
            *(float4*)(k_s + r * 128 + d4 * 4) = *(const float4*)(base + HID_ + g * D_ + d4 * 4);
            *(float4*)(v_s + r * 128 + d4 * 4) = *(const float4*)(base + HID_ + KV_ * D_ + g * D_ + d4 * 4);
        }
        __syncthreads();

        float s[64];
        #pragma unroll
        for (int j = 0; j < 64; ++j) s[j] = 0.f;
        for (int d4 = 0; d4 < 32; ++d4) {            // dynamic loop, regs stay static-indexed
            float4 q4 = *(const float4*)(qrow + d4 * 4);
            #pragma unroll
            for (int j = 0; j < 64; ++j) {
                float4 k4 = *(const float4*)(k_s + j * 128 + d4 * 4);  // broadcast LDS.128
                s[j] += q4.x * k4.x;
                s[j] += q4.y * k4.y;
                s[j] += q4.z * k4.z;
                s[j] += q4.w * k4.w;
            }
        }

        const int kb64 = kb * 64;
        #pragma unroll
        for (int j = 0; j < 64; ++j)
            if (kb64 + j > qpos) s[j] = -1e30f;      // causal mask

        float mn = m;
        #pragma unroll
        for (int j = 0; j < 64; ++j) mn = fmaxf(mn, s[j]);
        float alpha = __expf(m - mn);
        m = mn;
        float ps = 0.f;
        #pragma unroll
        for (int j = 0; j < 64; ++j) { s[j] = __expf(s[j] - mn); ps += s[j]; }
        l = l * alpha + ps;

        #pragma unroll
        for (int d = 0; d < 128; ++d) o[d] *= alpha;
        for (int j = 0; j < 64; ++j) {               // dynamic loop
            float pj = s[j];
            const float* vr = v_s + j * 128;
            #pragma unroll
            for (int d4 = 0; d4 < 32; ++d4) {
                float4 v4 = *(const float4*)(vr + d4 * 4);
                o[d4 * 4 + 0] += pj * v4.x;
                o[d4 * 4 + 1] += pj * v4.y;
                o[d4 * 4 + 2] += pj * v4.z;
                o[d4 * 4 + 3] += pj * v4.w;
            }
        }
    }

    float invl = 1.0f / l;
    float* op = attn + (size_t)(b * S_ + qb * 256 + tid) * HID_ + h * D_;
    #pragma unroll
    for (int d4 = 0; d4 < 32; ++d4)
        *(float4*)(op + d4 * 4) = make_float4(o[d4 * 4] * invl, o[d4 * 4 + 1] * invl,
                                              o[d4 * 4 + 2] * invl, o[d4 * 4 + 3] * invl);
}

// ---------------- per-token amax quantization ----------------
__device__ __forceinline__ signed char quant1(float x, float s) {
    float r = rintf(x / s);                  // round-half-even, matches jnp.round
    r = fminf(fmaxf(r, -127.f), 127.f);
    return (signed char)(int)r;
}

__global__ __launch_bounds__(256) void quant_kernel(const float* __restrict__ attn,
                                                    int8_t* __restrict__ q8,
                                                    float* __restrict__ ascale) {
    const int t = blockIdx.x, tid = threadIdx.x;
    const float4* row = (const float4*)(attn + (size_t)t * HID_);
    float4 v0 = row[tid], v1 = row[tid + 256], v2 = row[tid + 512], v3 = row[tid + 768];
    float mx = 0.f;
    mx = fmaxf(mx, fmaxf(fmaxf(fabsf(v0.x), fabsf(v0.y)), fmaxf(fabsf(v0.z), fabsf(v0.w))));
    mx = fmaxf(mx, fmaxf(fmaxf(fabsf(v1.x), fabsf(v1.y)), fmaxf(fabsf(v1.z), fabsf(v1.w))));
    mx = fmaxf(mx, fmaxf(fmaxf(fabsf(v2.x), fabsf(v2.y)), fmaxf(fabsf(v2.z), fabsf(v2.w))));
    mx = fmaxf(mx, fmaxf(fmaxf(fabsf(v3.x), fabsf(v3.y)), fmaxf(fabsf(v3.z), fabsf(v3.w))));
    #pragma unroll
    for (int off = 16; off; off >>= 1) mx = fmaxf(mx, __shfl_xor_sync(0xffffffffu, mx, off));
    __shared__ float red[8];
    if ((tid & 31) == 0) red[tid >> 5] = mx;
    __syncthreads();
    if (tid == 0) {
        float mm = red[0];
        #pragma unroll
        for (int i = 1; i < 8; ++i) mm = fmaxf(mm, red[i]);
        red[0] = fmaxf(mm, 1e-6f);
    }
    __syncthreads();
    float s = red[0] / 127.0f;               // a_scale = amax / 127 (exact division like ref)
    if (tid == 0) ascale[t] = s;
    char4* outp = (char4*)(q8 + (size_t)t * HID_);
    outp[tid]       = make_char4(quant1(v0.x, s), quant1(v0.y, s), quant1(v0.z, s), quant1(v0.w, s));
    outp[tid + 256] = make_char4(quant1(v1.x, s), quant1(v1.y, s), quant1(v1.z, s), quant1(v1.w, s));
    outp[tid + 512] = make_char4(quant1(v2.x, s), quant1(v2.y, s), quant1(v2.z, s), quant1(v2.w, s));
    outp[tid + 768] = make_char4(quant1(v3.x, s), quant1(v3.y, s), quant1(v3.z, s), quant1(v3.w, s));
}

// ---------------- launch ----------------
extern "C" void kernel_launch(void* const* d_in, const int* in_sizes, int n_in,
                              void* d_out, int out_size) {
    (void)in_sizes; (void)n_in; (void)out_size;
    const int*   q_hidden = (const int*)d_in[0];
    const float* q_scale  = (const float*)d_in[1];
    // d_in[2] = q_sum, unused by the reference math
    const int*   w_qkv    = (const int*)d_in[3];
    const float* s_qkv    = (const float*)d_in[4];
    const int*   w_o      = (const int*)d_in[5];
    const float* s_o      = (const float*)d_in[6];
    float* out = (float*)d_out;

    int8_t *x8, *wq8, *wo8, *aq8;
    float *qkv, *attn, *ascale;
    cudaGetSymbolAddress((void**)&x8,     g_x8);
    cudaGetSymbolAddress((void**)&wq8,    g_wqkv8);
    cudaGetSymbolAddress((void**)&wo8,    g_wo8);
    cudaGetSymbolAddress((void**)&aq8,    g_attnq);
    cudaGetSymbolAddress((void**)&qkv,    g_qkv);
    cudaGetSymbolAddress((void**)&attn,   g_attn);
    cudaGetSymbolAddress((void**)&ascale, g_ascale);

    pack_int8_kernel<<<(T_*HID_/4 + 255) / 256, 256>>>(q_hidden, x8, T_*HID_/4);
    pack_int8_kernel<<<(OUTQKV_*HID_/4 + 255) / 256, 256>>>(w_qkv, wq8, OUTQKV_*HID_/4);
    pack_int8_kernel<<<(HID_*HID_/4 + 255) / 256, 256>>>(w_o, wo8, HID_*HID_/4);

    gemm_s8_kernel<<<dim3(OUTQKV_/128, T_/128), 256>>>(x8, wq8, s_qkv, q_scale, qkv,
                                                       T_, OUTQKV_, HID_);
    rope_kernel<<<(T_*(H_+KV_)*64 + 255) / 256, 256>>>(qkv);

    const int attn_smem = (256 * 132 + 2 * 64 * 128) * sizeof(float);  // 200704 B
    cudaFuncSetAttribute(attn_kernel, cudaFuncAttributeMaxDynamicSharedMemorySize, attn_smem);
    attn_kernel<<<dim3(S_/256, H_, B_), 256, attn_smem>>>(qkv, attn);

    quant_kernel<<<T_, 256>>>(attn, aq8, ascale);
    gemm_s8_kernel<<<dim3(HID_/128, T_/128), 256>>>(aq8, wo8, s_o, ascale, out,
                                                    T_, HID_, HID_);
}

// round 8
// speedup vs baseline: 1.1808x; 1.1808x over previous
#include <cuda_runtime.h>
#include <cstdint>
#include <math.h>

#define B_ 2
#define S_ 2048
#define H_ 32
#define KV_ 8
#define D_ 128
#define T_ (B_*S_)                 // 4096
#define HID_ (H_*D_)               // 4096
#define OUTQKV_ ((H_+2*KV_)*D_)    // 6144

// ---------------- scratch (device globals; no allocation allowed) ----------------
__device__ int8_t g_x8[(size_t)T_*HID_];
__device__ int8_t g_wqkv8[(size_t)OUTQKV_*HID_];
__device__ int8_t g_wo8[(size_t)HID_*HID_];
__device__ float  g_qkv[(size_t)T_*OUTQKV_];
__device__ float  g_attn[(size_t)T_*HID_];
__device__ int8_t g_attnq[(size_t)T_*HID_];
__device__ float  g_ascale[T_];

// ---------------- f32x2 packed math helpers ----------------
#define FMA2(d,a,b) asm("fma.rn.f32x2 %0, %1, %2, %0;" : "+l"(d) : "l"(a), "l"(b))
#define MUL2(d,a,b) asm("mul.rn.f32x2 %0, %1, %2;" : "=l"(d) : "l"(a), "l"(b))

__device__ __forceinline__ unsigned long long pk2(float lo, float hi) {
    unsigned long long r;
    asm("mov.b64 %0, {%1,%2};" : "=l"(r) : "f"(lo), "f"(hi));
    return r;
}
__device__ __forceinline__ void upk2(float& lo, float& hi, unsigned long long v) {
    asm("mov.b64 {%0,%1}, %2;" : "=f"(lo), "=f"(hi) : "l"(v));
}

// ---------------- cp.async helpers ----------------
__device__ __forceinline__ void cp16(void* dst, const void* src) {
    unsigned d = (unsigned)__cvta_generic_to_shared(dst);
    asm volatile("cp.async.cg.shared.global [%0], [%1], 16;" :: "r"(d), "l"(src) : "memory");
}
__device__ __forceinline__ void cp4(void* dst, const void* src) {
    unsigned d = (unsigned)__cvta_generic_to_shared(dst);
    asm volatile("cp.async.ca.shared.global [%0], [%1], 4;" :: "r"(d), "l"(src) : "memory");
}
#define CP_COMMIT() asm volatile("cp.async.commit_group;" ::: "memory")
#define CP_WAIT(n)  asm volatile("cp.async.wait_group %0;" :: "n"(n) : "memory")

// ---------------- int32 -> int8 pack ----------------
__global__ void pack_int8_kernel(const int* __restrict__ in, int8_t* __restrict__ out, int n4) {
    int i = blockIdx.x * blockDim.x + threadIdx.x;
    if (i >= n4) return;
    int4 v = ((const int4*)in)[i];
    ((char4*)out)[i] = make_char4((signed char)v.x, (signed char)v.y,
                                  (signed char)v.z, (signed char)v.w);
}

// ---------------- block-scaled s8 GEMM (2-stage cp.async pipeline) ----------------
__device__ __forceinline__ void mma_s8(int c[4], const int a[4], const int b[2]) {
    asm volatile(
        "mma.sync.aligned.m16n8k32.row.col.s32.s8.s8.s32 "
        "{%0,%1,%2,%3}, {%4,%5,%6,%7}, {%8,%9}, {%0,%1,%2,%3};\n"
        : "+r"(c[0]), "+r"(c[1]), "+r"(c[2]), "+r"(c[3])
        : "r"(a[0]), "r"(a[1]), "r"(a[2]), "r"(a[3]), "r"(b[0]), "r"(b[1]));
}

#define GSTAGE 36864          // A(128*144) + B(128*144) bytes per stage
#define GSMEM_TOTAL (2*GSTAGE + 2*128*4)

__device__ __forceinline__ void gemm_load_stage(
    int8_t* dsm, const int8_t* A, const int8_t* Bm, const float* colscale,
    int bm0, int bn0, int K, int ng, int tid, int st, int grp)
{
    int8_t* sA = dsm + st * GSTAGE;
    int8_t* sB = sA + 18432;
    float*  sS = (float*)(dsm + 2 * GSTAGE) + st * 128;
    #pragma unroll
    for (int i = 0; i < 4; ++i) {
        int cidx = tid + i * 256;
        int r = cidx >> 3, c = (cidx & 7) << 4;
        cp16(sA + r * 144 + c, A  + (size_t)(bm0 + r) * K + (grp << 7) + c);
        cp16(sB + r * 144 + c, Bm + (size_t)(bn0 + r) * K + (grp << 7) + c);
    }
    if (tid < 128) cp4(sS + tid, colscale + (size_t)(bn0 + tid) * ng + grp);
}

__global__ __launch_bounds__(256, 1) void gemm_s8_kernel(
    const int8_t* __restrict__ A, const int8_t* __restrict__ Bm,
    const float* __restrict__ colscale, const float* __restrict__ rowscale,
    float* __restrict__ C, int M, int N, int K)
{
    extern __shared__ __align__(16) int8_t dsm[];

    const int tid  = threadIdx.x;
    const int warp = tid >> 5, lane = tid & 31;
    const int wm = warp >> 2, wn = warp & 3;
    const int g  = lane >> 2, tg = lane & 3;
    const int bm0 = blockIdx.y * 128, bn0 = blockIdx.x * 128;
    const int ng = K >> 7;

    float facc[4][4][4];
    #pragma unroll
    for (int mt = 0; mt < 4; ++mt)
        #pragma unroll
        for (int nt = 0; nt < 4; ++nt)
            #pragma unroll
            for (int e = 0; e < 4; ++e) facc[mt][nt][e] = 0.f;

    gemm_load_stage(dsm, A, Bm, colscale, bm0, bn0, K, ng, tid, 0, 0);
    CP_COMMIT();

    for (int grp = 0; grp < ng; ++grp) {
        const int st = grp & 1;
        if (grp + 1 < ng) {
            gemm_load_stage(dsm, A, Bm, colscale, bm0, bn0, K, ng, tid, st ^ 1, grp + 1);
            CP_COMMIT();
            CP_WAIT(1);
        } else {
            CP_WAIT(0);
        }
        __syncthreads();

        const int8_t* smA = dsm + st * GSTAGE;
        const int8_t* smB = smA + 18432;
        const float*  sS  = (const float*)(dsm + 2 * GSTAGE) + st * 128;

        int iacc[4][4][4];
        #pragma unroll
        for (int mt = 0; mt < 4; ++mt)
            #pragma unroll
            for (int nt = 0; nt < 4; ++nt)
                #pragma unroll
                for (int e = 0; e < 4; ++e) iacc[mt][nt][e] = 0;

        #pragma unroll
        for (int ks = 0; ks < 4; ++ks) {
            int a[4][4], b[4][2];
            #pragma unroll
            for (int mt = 0; mt < 4; ++mt) {
                const int8_t* p = smA + (wm * 64 + mt * 16 + g) * 144 + ks * 32 + tg * 4;
                a[mt][0] = *(const int*)(p);
                a[mt][1] = *(const int*)(p + 8 * 144);
                a[mt][2] = *(const int*)(p + 16);
                a[mt][3] = *(const int*)(p + 8 * 144 + 16);
            }
            #pragma unroll
            for (int nt = 0; nt < 4; ++nt) {
                const int8_t* p = smB + (wn * 32 + nt * 8 + g) * 144 + ks * 32 + tg * 4;
                b[nt][0] = *(const int*)(p);
                b[nt][1] = *(const int*)(p + 16);
            }
            #pragma unroll
            for (int mt = 0; mt < 4; ++mt)
                #pragma unroll
                for (int nt = 0; nt < 4; ++nt)
                    mma_s8(iacc[mt][nt], a[mt], b[nt]);
        }

        #pragma unroll
        for (int mt = 0; mt < 4; ++mt)
            #pragma unroll
            for (int nt = 0; nt < 4; ++nt) {
                int colb = wn * 32 + nt * 8 + tg * 2;
                float s0 = sS[colb], s1 = sS[colb + 1];
                facc[mt][nt][0] += (float)iacc[mt][nt][0] * s0;
                facc[mt][nt][1] += (float)iacc[mt][nt][1] * s1;
                facc[mt][nt][2] += (float)iacc[mt][nt][2] * s0;
                facc[mt][nt][3] += (float)iacc[mt][nt][3] * s1;
            }
        __syncthreads();
    }

    #pragma unroll
    for (int mt = 0; mt < 4; ++mt) {
        int r0 = bm0 + wm * 64 + mt * 16 + g;
        float rs0 = rowscale[r0], rs1 = rowscale[r0 + 8];
        #pragma unroll
        for (int nt = 0; nt < 4; ++nt) {
            int col = bn0 + wn * 32 + nt * 8 + tg * 2;
            *(float2*)(C + (size_t)r0 * N + col) =
                make_float2(facc[mt][nt][0] * rs0, facc[mt][nt][1] * rs0);
            *(float2*)(C + (size_t)(r0 + 8) * N + col) =
                make_float2(facc[mt][nt][2] * rs1, facc[mt][nt][3] * rs1);
        }
    }
}

// ---------------- RoPE (NeoX) in place ----------------
__global__ void rope_kernel(float* __restrict__ qkv) {
    int idx = blockIdx.x * 256 + threadIdx.x;
    if (idx >= T_ * (H_ + KV_) * 64) return;
    int i  = idx & 63;
    int hh = (idx >> 6) % (H_ + KV_);
    int t  = idx / ((H_ + KV_) * 64);
    int s  = t & (S_ - 1);
    int col = (hh < H_) ? hh * D_ : HID_ + (hh - H_) * D_;
    // 1/theta^(i/64) = 2^(-i * log2(1e6)/64)
    float inv = exp2f((float)i * -0.31143075889569023f);
    float ang = (float)s * inv;
    float sn, c;
    sincosf(ang, &sn, &c);
    float* p = qkv + (size_t)t * OUTQKV_ + col;
    float x1 = p[i], x2 = p[i + 64];
    p[i]      = x1 * c - x2 * sn;
    p[i + 64] = x2 * c + x1 * sn;
}

// ---------------- split-D f32x2 causal flash attention ----------------
// Block: 256 threads = 8 warps. Warps 0-3: dims [0,64) of queries; warps 4-7: dims [64,128).
// QB=128 queries per block, KB=32 keys per tile.
#define QB 128
#define KB 32
#define QPAD 68
// smem floats: q[2][QB][68] | k[2][KB][68] | v[2][KB][68] | part[QB][33] | alpha[QB]
#define ATTN_SMEM_FLOATS (2*QB*QPAD + 2*KB*QPAD + 2*KB*QPAD + QB*33 + QB)

__global__ __launch_bounds__(256, 1) void attn_kernel(const float* __restrict__ qkv,
                                                      float* __restrict__ attn) {
    extern __shared__ float sm[];
    float* q_s     = sm;
    float* k_s     = q_s + 2 * QB * QPAD;
    float* v_s     = k_s + 2 * KB * QPAD;
    float* part    = v_s + 2 * KB * QPAD;   // [QB][33]
    float* alpha_s = part + QB * 33;        // [QB]

    const int tid = threadIdx.x;
    const int warp = tid >> 5, lane = tid & 31;
    const int half = warp >> 2;                 // 0 or 1
    const int q = ((warp & 3) << 5) | lane;     // 0..127
    const int qb = blockIdx.x, h = blockIdx.y, b = blockIdx.z;
    const int g = h >> 2;
    const int q0 = qb * QB;
    const int qpos = q0 + q;
    const float scale = 0.08838834764831845f;

    // load q block (scale-premultiplied), split by dim-half
    for (int i = tid; i < QB * 32; i += 256) {
        int r = i >> 5, c = i & 31;             // c: float4 index over 128 dims
        int hh = c >> 4, cc = c & 15;
        float4 v = *(const float4*)(qkv + (size_t)(b * S_ + q0 + r) * OUTQKV_ + h * D_ + c * 4);
        v.x *= scale; v.y *= scale; v.z *= scale; v.w *= scale;
        *(float4*)(q_s + hh * (QB * QPAD) + r * QPAD + cc * 4) = v;
    }

    unsigned long long o2[32];
    #pragma unroll
    for (int i = 0; i < 32; ++i) o2[i] = 0ull;
    float m = -1e30f, l = 0.f;

    const float* qrow = q_s + half * (QB * QPAD) + q * QPAD;
    const float* kh = k_s + half * (KB * QPAD);
    const float* vh = v_s + half * (KB * QPAD);
    const int nkb = (q0 + QB) / KB;

    for (int kb = 0; kb < nkb; ++kb) {
        __syncthreads();                        // previous tile fully consumed
        // cooperative k/v tile load (each half loads its dims)
        for (int i = tid; i < KB * 32 * 2; i += 256) {
            int arr = i >> 10, rem = i & 1023;
            int r = rem >> 5, c = rem & 31;
            int hh = c >> 4, cc = c & 15;
            const float* src = qkv + (size_t)(b * S_ + kb * KB + r) * OUTQKV_
                             + HID_ + arr * (KV_ * D_) + g * D_ + c * 4;
            float* dst = (arr ? v_s : k_s) + hh * (KB * QPAD) + r * QPAD + cc * 4;
            *(float4*)dst = *(const float4*)src;
        }
        __syncthreads();

        // ---- QK over this thread's 64 dims: s2[j] packed accumulators ----
        unsigned long long s2[32];
        #pragma unroll
        for (int j = 0; j < 32; ++j) s2[j] = 0ull;
        for (int dg = 0; dg < 16; ++dg) {       // dynamic: addresses only
            double2 qd = *(const double2*)(qrow + dg * 4);
            unsigned long long q01 = __double_as_longlong(qd.x);
            unsigned long long q23 = __double_as_longlong(qd.y);
            #pragma unroll
            for (int j = 0; j < 32; ++j) {
                double2 kd = *(const double2*)(kh + j * QPAD + dg * 4);  // broadcast
                FMA2(s2[j], q01, __double_as_longlong(kd.x));
                FMA2(s2[j], q23, __double_as_longlong(kd.y));
            }
        }
        float s[32];
        #pragma unroll
        for (int j = 0; j < 32; ++j) { float lo, hi; upk2(lo, hi, s2[j]); s[j] = lo + hi; }

        // ---- cross-half reduction + softmax (half 0 owns state) ----
        if (half == 1) {
            #pragma unroll
            for (int j = 0; j < 32; ++j) part[q * 33 + j] = s[j];
        }
        __syncthreads();
        float alpha = 0.f;
        if (half == 0) {
            const int kbase = kb * KB;
            #pragma unroll
            for (int j = 0; j < 32; ++j) {
                float t = s[j] + part[q * 33 + j];
                s[j] = (kbase + j > qpos) ? -1e30f : t;
            }
            float mn = m;
            #pragma unroll
            for (int j = 0; j < 32; ++j) mn = fmaxf(mn, s[j]);
            alpha = __expf(m - mn);
            m = mn;
            float ps = 0.f;
            #pragma unroll
            for (int j = 0; j < 32; ++j) { s[j] = __expf(s[j] - mn); ps += s[j]; }
            l = l * alpha + ps;
            #pragma unroll
            for (int j = 0; j < 32; ++j) part[q * 33 + j] = s[j];
            alpha_s[q] = alpha;
        }
        __syncthreads();
        if (half == 1) alpha = alpha_s[q];

        // ---- rescale + PV over this thread's 64 dims ----
        unsigned long long a2 = pk2(alpha, alpha);
        #pragma unroll
        for (int i = 0; i < 32; ++i) MUL2(o2[i], o2[i], a2);

        for (int j = 0; j < 32; ++j) {          // dynamic j: p from smem
            float pj = part[q * 33 + j];
            unsigned long long p2 = pk2(pj, pj);
            const float* vr = vh + j * QPAD;
            #pragma unroll
            for (int dg = 0; dg < 16; ++dg) {
                double2 vd = *(const double2*)(vr + dg * 4);   // broadcast
                FMA2(o2[2 * dg],     p2, __double_as_longlong(vd.x));
                FMA2(o2[2 * dg + 1], p2, __double_as_longlong(vd.y));
            }
        }
    }

    if (half == 0) alpha_s[q] = 1.0f / l;
    __syncthreads();
    float invl = alpha_s[q];
    float* op = attn + (size_t)(b * S_ + qpos) * HID_ + h * D_ + half * 64;
    #pragma unroll
    for (int i = 0; i < 32; ++i) {
        float lo, hi; upk2(lo, hi, o2[i]);
        *(float2*)(op + i * 2) = make_float2(lo * invl, hi * invl);
    }
}

// ---------------- per-token amax quantization ----------------
__device__ __forceinline__ signed char quant1(float x, float s) {
    float r = rintf(x / s);
    r = fminf(fmaxf(r, -127.f), 127.f);
    return (signed char)(int)r;
}

__global__ __launch_bounds__(256) void quant_kernel(const float* __restrict__ attn,
                                                    int8_t* __restrict__ q8,
                                                    float* __restrict__ ascale) {
    const int t = blockIdx.x, tid = threadIdx.x;
    const float4* row = (const float4*)(attn + (size_t)t * HID_);
    float4 v0 = row[tid], v1 = row[tid + 256], v2 = row[tid + 512], v3 = row[tid + 768];
    float mx = 0.f;
    mx = fmaxf(mx, fmaxf(fmaxf(fabsf(v0.x), fabsf(v0.y)), fmaxf(fabsf(v0.z), fabsf(v0.w))));
    mx = fmaxf(mx, fmaxf(fmaxf(fabsf(v1.x), fabsf(v1.y)), fmaxf(fabsf(v1.z), fabsf(v1.w))));
    mx = fmaxf(mx, fmaxf(fmaxf(fabsf(v2.x), fabsf(v2.y)), fmaxf(fabsf(v2.z), fabsf(v2.w))));
    mx = fmaxf(mx, fmaxf(fmaxf(fabsf(v3.x), fabsf(v3.y)), fmaxf(fabsf(v3.z), fabsf(v3.w))));
    #pragma unroll
    for (int off = 16; off; off >>= 1) mx = fmaxf(mx, __shfl_xor_sync(0xffffffffu, mx, off));
    __shared__ float red[8];
    if ((tid & 31) == 0) red[tid >> 5] = mx;
    __syncthreads();
    if (tid == 0) {
        float mm = red[0];
        #pragma unroll
        for (int i = 1; i < 8; ++i) mm = fmaxf(mm, red[i]);
        red[0] = fmaxf(mm, 1e-6f);
    }
    __syncthreads();
    float s = red[0] / 127.0f;
    if (tid == 0) ascale[t] = s;
    char4* outp = (char4*)(q8 + (size_t)t * HID_);
    outp[tid]       = make_char4(quant1(v0.x, s), quant1(v0.y, s), quant1(v0.z, s), quant1(v0.w, s));
    outp[tid + 256] = make_char4(quant1(v1.x, s), quant1(v1.y, s), quant1(v1.z, s), quant1(v1.w, s));
    outp[tid + 512] = make_char4(quant1(v2.x, s), quant1(v2.y, s), quant1(v2.z, s), quant1(v2.w, s));
    outp[tid + 768] = make_char4(quant1(v3.x, s), quant1(v3.y, s), quant1(v3.z, s), quant1(v3.w, s));
}

// ---------------- launch ----------------
extern "C" void kernel_launch(void* const* d_in, const int* in_sizes, int n_in,
                              void* d_out, int out_size) {
    (void)in_sizes; (void)n_in; (void)out_size;
    const int*   q_hidden = (const int*)d_in[0];
    const float* q_scale  = (const float*)d_in[1];
    const int*   w_qkv    = (const int*)d_in[3];
    const float* s_qkv    = (const float*)d_in[4];
    const int*   w_o      = (const int*)d_in[5];
    const float* s_o      = (const float*)d_in[6];
    float* out = (float*)d_out;

    int8_t *x8, *wq8, *wo8, *aq8;
    float *qkv, *attn, *ascale;
    cudaGetSymbolAddress((void**)&x8,     g_x8);
    cudaGetSymbolAddress((void**)&wq8,    g_wqkv8);
    cudaGetSymbolAddress((void**)&wo8,    g_wo8);
    cudaGetSymbolAddress((void**)&aq8,    g_attnq);
    cudaGetSymbolAddress((void**)&qkv,    g_qkv);
    cudaGetSymbolAddress((void**)&attn,   g_attn);
    cudaGetSymbolAddress((void**)&ascale, g_ascale);

    pack_int8_kernel<<<(T_*HID_/4 + 255) / 256, 256>>>(q_hidden, x8, T_*HID_/4);
    pack_int8_kernel<<<(OUTQKV_*HID_/4 + 255) / 256, 256>>>(w_qkv, wq8, OUTQKV_*HID_/4);
    pack_int8_kernel<<<(HID_*HID_/4 + 255) / 256, 256>>>(w_o, wo8, HID_*HID_/4);

    cudaFuncSetAttribute(gemm_s8_kernel, cudaFuncAttributeMaxDynamicSharedMemorySize, GSMEM_TOTAL);
    gemm_s8_kernel<<<dim3(OUTQKV_/128, T_/128), 256, GSMEM_TOTAL>>>(
        x8, wq8, s_qkv, q_scale, qkv, T_, OUTQKV_, HID_);

    rope_kernel<<<(T_*(H_+KV_)*64 + 255) / 256, 256>>>(qkv);

    const int attn_smem = ATTN_SMEM_FLOATS * sizeof(float);  // 121856 B
    cudaFuncSetAttribute(attn_kernel, cudaFuncAttributeMaxDynamicSharedMemorySize, attn_smem);
    attn_kernel<<<dim3(S_/QB, H_, B_), 256, attn_smem>>>(qkv, attn);

    quant_kernel<<<T_, 256>>>(attn, aq8, ascale);

    gemm_s8_kernel<<<dim3(HID_/128, T_/128), 256, GSMEM_TOTAL>>>(
        aq8, wo8, s_o, ascale, out, T_, HID_, HID_);
}

// round 11
// speedup vs baseline: 1.2380x; 1.0484x over previous
#include <cuda_runtime.h>
#include <cstdint>
#include <math.h>

#define B_ 2
#define S_ 2048
#define H_ 32
#define KV_ 8
#define D_ 128
#define T_ (B_*S_)                 // 4096
#define HID_ (H_*D_)               // 4096
#define OUTQKV_ ((H_+2*KV_)*D_)    // 6144

// ---------------- scratch (device globals; no allocation allowed) ----------------
__device__ int8_t g_x8[(size_t)T_*HID_];
__device__ int8_t g_wqkv8[(size_t)OUTQKV_*HID_];
__device__ int8_t g_wo8[(size_t)HID_*HID_];
__device__ float  g_qkv[(size_t)T_*OUTQKV_];
__device__ float  g_attn[(size_t)T_*HID_];
__device__ int8_t g_attnq[(size_t)T_*HID_];
__device__ float  g_ascale[T_];

// ---------------- f32x2 packed math helpers ----------------
#define FMA2(d,a,b) asm("fma.rn.f32x2 %0, %1, %2, %0;" : "+l"(d) : "l"(a), "l"(b))
#define MUL2(d,a,b) asm("mul.rn.f32x2 %0, %1, %2;" : "=l"(d) : "l"(a), "l"(b))

__device__ __forceinline__ unsigned long long pk2(float lo, float hi) {
    unsigned long long r;
    asm("mov.b64 %0, {%1,%2};" : "=l"(r) : "f"(lo), "f"(hi));
    return r;
}
__device__ __forceinline__ void upk2(float& lo, float& hi, unsigned long long v) {
    asm("mov.b64 {%0,%1}, %2;" : "=f"(lo), "=f"(hi) : "l"(v));
}

// ---------------- cp.async helpers ----------------
__device__ __forceinline__ void cp16(void* dst, const void* src) {
    unsigned d = (unsigned)__cvta_generic_to_shared(dst);
    asm volatile("cp.async.cg.shared.global [%0], [%1], 16;" :: "r"(d), "l"(src) : "memory");
}
__device__ __forceinline__ void cp4(void* dst, const void* src) {
    unsigned d = (unsigned)__cvta_generic_to_shared(dst);
    asm volatile("cp.async.ca.shared.global [%0], [%1], 4;" :: "r"(d), "l"(src) : "memory");
}
#define CP_COMMIT() asm volatile("cp.async.commit_group;" ::: "memory")
#define CP_WAIT(n)  asm volatile("cp.async.wait_group %0;" :: "n"(n) : "memory")

// ---------------- int32 -> int8 pack ----------------
__global__ void pack_int8_kernel(const int* __restrict__ in, int8_t* __restrict__ out, int n4) {
    int i = blockIdx.x * blockDim.x + threadIdx.x;
    if (i >= n4) return;
    int4 v = ((const int4*)in)[i];
    ((char4*)out)[i] = make_char4((signed char)v.x, (signed char)v.y,
                                  (signed char)v.z, (signed char)v.w);
}

// ---------------- block-scaled s8 GEMM ----------------
// 128(M) x 64(N) CTA tile, BK=128 (one scale group), 2-stage cp.async,
// 2 CTAs/SM to fill tensor-pipe bubbles. 8 warps: wm=warp&3 (32 rows), wn=warp>>2 (32 cols).
__device__ __forceinline__ void mma_s8(int c[4], const int a[4], const int b[2]) {
    asm volatile(
        "mma.sync.aligned.m16n8k32.row.col.s32.s8.s8.s32 "
        "{%0,%1,%2,%3}, {%4,%5,%6,%7}, {%8,%9}, {%0,%1,%2,%3};\n"
        : "+r"(c[0]), "+r"(c[1]), "+r"(c[2]), "+r"(c[3])
        : "r"(a[0]), "r"(a[1]), "r"(a[2]), "r"(a[3]), "r"(b[0]), "r"(b[1]));
}

#define GST2 27648                          // A(128*144) + B(64*144) per stage
#define GSMEM2 (2*GST2 + 2*64*4)            // + 2-stage col scales

__device__ __forceinline__ void gemm_load_stage(
    int8_t* dsm, const int8_t* A, const int8_t* Bm, const float* colscale,
    int bm0, int bn0, int K, int ng, int tid, int st, int grp)
{
    int8_t* sA = dsm + st * GST2;
    int8_t* sB = sA + 18432;
    float*  sS = (float*)(dsm + 2 * GST2) + st * 64;
    #pragma unroll
    for (int i = 0; i < 6; ++i) {
        int cidx = tid + i * 256;           // 0..1535: 1024 A chunks + 512 B chunks
        if (cidx < 1024) {
            int r = cidx >> 3, c = (cidx & 7) << 4;
            cp16(sA + r * 144 + c, A + (size_t)(bm0 + r) * K + (grp << 7) + c);
        } else {
            int j = cidx - 1024;
            int r = j >> 3, c = (j & 7) << 4;
            cp16(sB + r * 144 + c, Bm + (size_t)(bn0 + r) * K + (grp << 7) + c);
        }
    }
    if (tid < 64) cp4(sS + tid, colscale + (size_t)(bn0 + tid) * ng + grp);
}

__global__ __launch_bounds__(256, 2) void gemm_s8_kernel(
    const int8_t* __restrict__ A, const int8_t* __restrict__ Bm,
    const float* __restrict__ colscale, const float* __restrict__ rowscale,
    float* __restrict__ C, int M, int N, int K)
{
    extern __shared__ __align__(16) int8_t dsm[];

    const int tid  = threadIdx.x;
    const int warp = tid >> 5, lane = tid & 31;
    const int wm = warp & 3, wn = warp >> 2;     // 4 x 2 warp grid (32x32 each)
    const int g  = lane >> 2, tg = lane & 3;
    const int bm0 = blockIdx.y * 128, bn0 = blockIdx.x * 64;
    const int ng = K >> 7;

    float facc[2][4][4];
    #pragma unroll
    for (int mt = 0; mt < 2; ++mt)
        #pragma unroll
        for (int nt = 0; nt < 4; ++nt)
            #pragma unroll
            for (int e = 0; e < 4; ++e) facc[mt][nt][e] = 0.f;

    gemm_load_stage(dsm, A, Bm, colscale, bm0, bn0, K, ng, tid, 0, 0);
    CP_COMMIT();

    for (int grp = 0; grp < ng; ++grp) {
        const int st = grp & 1;
        if (grp + 1 < ng) {
            gemm_load_stage(dsm, A, Bm, colscale, bm0, bn0, K, ng, tid, st ^ 1, grp + 1);
            CP_COMMIT();
            CP_WAIT(1);
        } else {
            CP_WAIT(0);
        }
        __syncthreads();

        const int8_t* smA = dsm + st * GST2;
        const int8_t* smB = smA + 18432;
        const float*  sS  = (const float*)(dsm + 2 * GST2) + st * 64;

        int iacc[2][4][4];
        #pragma unroll
        for (int mt = 0; mt < 2; ++mt)
            #pragma unroll
            for (int nt = 0; nt < 4; ++nt)
                #pragma unroll
                for (int e = 0; e < 4; ++e) iacc[mt][nt][e] = 0;

        #pragma unroll
        for (int ks = 0; ks < 4; ++ks) {
            int a[2][4], b[4][2];
            #pragma unroll
            for (int mt = 0; mt < 2; ++mt) {
                const int8_t* p = smA + (wm * 32 + mt * 16 + g) * 144 + ks * 32 + tg * 4;
                a[mt][0] = *(const int*)(p);
                a[mt][1] = *(const int*)(p + 8 * 144);
                a[mt][2] = *(const int*)(p + 16);
                a[mt][3] = *(const int*)(p + 8 * 144 + 16);
            }
            #pragma unroll
            for (int nt = 0; nt < 4; ++nt) {
                const int8_t* p = smB + (wn * 32 + nt * 8 + g) * 144 + ks * 32 + tg * 4;
                b[nt][0] = *(const int*)(p);
                b[nt][1] = *(const int*)(p + 16);
            }
            #pragma unroll
            for (int mt = 0; mt < 2; ++mt)
                #pragma unroll
                for (int nt = 0; nt < 4; ++nt)
                    mma_s8(iacc[mt][nt], a[mt], b[nt]);
        }

        #pragma unroll
        for (int mt = 0; mt < 2; ++mt)
            #pragma unroll
            for (int nt = 0; nt < 4; ++nt) {
                int colb = wn * 32 + nt * 8 + tg * 2;
                float s0 = sS[colb], s1 = sS[colb + 1];
                facc[mt][nt][0] += (float)iacc[mt][nt][0] * s0;
                facc[mt][nt][1] += (float)iacc[mt][nt][1] * s1;
                facc[mt][nt][2] += (float)iacc[mt][nt][2] * s0;
                facc[mt][nt][3] += (float)iacc[mt][nt][3] * s1;
            }
        __syncthreads();   // stage st fully consumed before next-next load overwrites it
    }

    #pragma unroll
    for (int mt = 0; mt < 2; ++mt) {
        int r0 = bm0 + wm * 32 + mt * 16 + g;
        float rs0 = rowscale[r0], rs1 = rowscale[r0 + 8];
        #pragma unroll
        for (int nt = 0; nt < 4; ++nt) {
            int col = bn0 + wn * 32 + nt * 8 + tg * 2;
            *(float2*)(C + (size_t)r0 * N + col) =
                make_float2(facc[mt][nt][0] * rs0, facc[mt][nt][1] * rs0);
            *(float2*)(C + (size_t)(r0 + 8) * N + col) =
                make_float2(facc[mt][nt][2] * rs1, facc[mt][nt][3] * rs1);
        }
    }
}

// ---------------- RoPE (NeoX) in place ----------------
__global__ void rope_kernel(float* __restrict__ qkv) {
    int idx = blockIdx.x * 256 + threadIdx.x;
    if (idx >= T_ * (H_ + KV_) * 64) return;
    int i  = idx & 63;
    int hh = (idx >> 6) % (H_ + KV_);
    int t  = idx / ((H_ + KV_) * 64);
    int s  = t & (S_ - 1);
    int col = (hh < H_) ? hh * D_ : HID_ + (hh - H_) * D_;
    float inv = exp2f((float)i * -0.31143075889569023f);
    float ang = (float)s * inv;
    float sn, c;
    sincosf(ang, &sn, &c);
    float* p = qkv + (size_t)t * OUTQKV_ + col;
    float x1 = p[i], x2 = p[i + 64];
    p[i]      = x1 * c - x2 * sn;
    p[i + 64] = x2 * c + x1 * sn;
}

// ---------------- split-D f32x2 causal flash attention (R7, passing) ----------------
#define QB 128
#define KB 32
#define QPAD 68
#define ATTN_SMEM_FLOATS (2*QB*QPAD + 2*KB*QPAD + 2*KB*QPAD + QB*33 + QB)

__global__ __launch_bounds__(256, 1) void attn_kernel(const float* __restrict__ qkv,
                                                      float* __restrict__ attn) {
    extern __shared__ float sm[];
    float* q_s     = sm;
    float* k_s     = q_s + 2 * QB * QPAD;
    float* v_s     = k_s + 2 * KB * QPAD;
    float* part    = v_s + 2 * KB * QPAD;
    float* alpha_s = part + QB * 33;

    const int tid = threadIdx.x;
    const int warp = tid >> 5, lane = tid & 31;
    const int half = warp >> 2;
    const int q = ((warp & 3) << 5) | lane;
    const int qb = blockIdx.x, h = blockIdx.y, b = blockIdx.z;
    const int g = h >> 2;
    const int q0 = qb * QB;
    const int qpos = q0 + q;
    const float scale = 0.08838834764831845f;

    for (int i = tid; i < QB * 32; i += 256) {
        int r = i >> 5, c = i & 31;
        int hh = c >> 4, cc = c & 15;
        float4 v = *(const float4*)(qkv + (size_t)(b * S_ + q0 + r) * OUTQKV_ + h * D_ + c * 4);
        v.x *= scale; v.y *= scale; v.z *= scale; v.w *= scale;
        *(float4*)(q_s + hh * (QB * QPAD) + r * QPAD + cc * 4) = v;
    }

    unsigned long long o2[32];
    #pragma unroll
    for (int i = 0; i < 32; ++i) o2[i] = 0ull;
    float m = -1e30f, l = 0.f;

    const float* qrow = q_s + half * (QB * QPAD) + q * QPAD;
    const float* kh = k_s + half * (KB * QPAD);
    const float* vh = v_s + half * (KB * QPAD);
    const int nkb = (q0 + QB) / KB;

    for (int kb = 0; kb < nkb; ++kb) {
        __syncthreads();
        for (int i = tid; i < KB * 32 * 2; i += 256) {
            int arr = i >> 10, rem = i & 1023;
            int r = rem >> 5, c = rem & 31;
            int hh = c >> 4, cc = c & 15;
            const float* src = qkv + (size_t)(b * S_ + kb * KB + r) * OUTQKV_
                             + HID_ + arr * (KV_ * D_) + g * D_ + c * 4;
            float* dst = (arr ? v_s : k_s) + hh * (KB * QPAD) + r * QPAD + cc * 4;
            *(float4*)dst = *(const float4*)src;
        }
        __syncthreads();

        unsigned long long s2[32];
        #pragma unroll
        for (int j = 0; j < 32; ++j) s2[j] = 0ull;
        for (int dg = 0; dg < 16; ++dg) {
            double2 qd = *(const double2*)(qrow + dg * 4);
            unsigned long long q01 = __double_as_longlong(qd.x);
            unsigned long long q23 = __double_as_longlong(qd.y);
            #pragma unroll
            for (int j = 0; j < 32; ++j) {
                double2 kd = *(const double2*)(kh + j * QPAD + dg * 4);
                FMA2(s2[j], q01, __double_as_longlong(kd.x));
                FMA2(s2[j], q23, __double_as_longlong(kd.y));
            }
        }
        float s[32];
        #pragma unroll
        for (int j = 0; j < 32; ++j) { float lo, hi; upk2(lo, hi, s2[j]); s[j] = lo + hi; }

        if (half == 1) {
            #pragma unroll
            for (int j = 0; j < 32; ++j) part[q * 33 + j] = s[j];
        }
        __syncthreads();
        float alpha = 0.f;
        if (half == 0) {
            const int kbase = kb * KB;
            #pragma unroll
            for (int j = 0; j < 32; ++j) {
                float t = s[j] + part[q * 33 + j];
                s[j] = (kbase + j > qpos) ? -1e30f : t;
            }
            float mn = m;
            #pragma unroll
            for (int j = 0; j < 32; ++j) mn = fmaxf(mn, s[j]);
            alpha = __expf(m - mn);
            m = mn;
            float ps = 0.f;
            #pragma unroll
            for (int j = 0; j < 32; ++j) { s[j] = __expf(s[j] - mn); ps += s[j]; }
            l = l * alpha + ps;
            #pragma unroll
            for (int j = 0; j < 32; ++j) part[q * 33 + j] = s[j];
            alpha_s[q] = alpha;
        }
        __syncthreads();
        if (half == 1) alpha = alpha_s[q];

        unsigned long long a2 = pk2(alpha, alpha);
        #pragma unroll
        for (int i = 0; i < 32; ++i) MUL2(o2[i], o2[i], a2);

        for (int j = 0; j < 32; ++j) {
            float pj = part[q * 33 + j];
            unsigned long long p2 = pk2(pj, pj);
            const float* vr = vh + j * QPAD;
            #pragma unroll
            for (int dg = 0; dg < 16; ++dg) {
                double2 vd = *(const double2*)(vr + dg * 4);
                FMA2(o2[2 * dg],     p2, __double_as_longlong(vd.x));
                FMA2(o2[2 * dg + 1], p2, __double_as_longlong(vd.y));
            }
        }
    }

    if (half == 0) alpha_s[q] = 1.0f / l;
    __syncthreads();
    float invl = alpha_s[q];
    float* op = attn + (size_t)(b * S_ + qpos) * HID_ + h * D_ + half * 64;
    #pragma unroll
    for (int i = 0; i < 32; ++i) {
        float lo, hi; upk2(lo, hi, o2[i]);
        *(float2*)(op + i * 2) = make_float2(lo * invl, hi * invl);
    }
}

// ---------------- per-token amax quantization ----------------
__device__ __forceinline__ signed char quant1(float x, float s) {
    float r = rintf(x / s);
    r = fminf(fmaxf(r, -127.f), 127.f);
    return (signed char)(int)r;
}

__global__ __launch_bounds__(256) void quant_kernel(const float* __restrict__ attn,
                                                    int8_t* __restrict__ q8,
                                                    float* __restrict__ ascale) {
    const int t = blockIdx.x, tid = threadIdx.x;
    const float4* row = (const float4*)(attn + (size_t)t * HID_);
    float4 v0 = row[tid], v1 = row[tid + 256], v2 = row[tid + 512], v3 = row[tid + 768];
    float mx = 0.f;
    mx = fmaxf(mx, fmaxf(fmaxf(fabsf(v0.x), fabsf(v0.y)), fmaxf(fabsf(v0.z), fabsf(v0.w))));
    mx = fmaxf(mx, fmaxf(fmaxf(fabsf(v1.x), fabsf(v1.y)), fmaxf(fabsf(v1.z), fabsf(v1.w))));
    mx = fmaxf(mx, fmaxf(fmaxf(fabsf(v2.x), fabsf(v2.y)), fmaxf(fabsf(v2.z), fabsf(v2.w))));
    mx = fmaxf(mx, fmaxf(fmaxf(fabsf(v3.x), fabsf(v3.y)), fmaxf(fabsf(v3.z), fabsf(v3.w))));
    #pragma unroll
    for (int off = 16; off; off >>= 1) mx = fmaxf(mx, __shfl_xor_sync(0xffffffffu, mx, off));
    __shared__ float red[8];
    if ((tid & 31) == 0) red[tid >> 5] = mx;
    __syncthreads();
    if (tid == 0) {
        float mm = red[0];
        #pragma unroll
        for (int i = 1; i < 8; ++i) mm = fmaxf(mm, red[i]);
        red[0] = fmaxf(mm, 1e-6f);
    }
    __syncthreads();
    float s = red[0] / 127.0f;
    if (tid == 0) ascale[t] = s;
    char4* outp = (char4*)(q8 + (size_t)t * HID_);
    outp[tid]       = make_char4(quant1(v0.x, s), quant1(v0.y, s), quant1(v0.z, s), quant1(v0.w, s));
    outp[tid + 256] = make_char4(quant1(v1.x, s), quant1(v1.y, s), quant1(v1.z, s), quant1(v1.w, s));
    outp[tid + 512] = make_char4(quant1(v2.x, s), quant1(v2.y, s), quant1(v2.z, s), quant1(v2.w, s));
    outp[tid + 768] = make_char4(quant1(v3.x, s), quant1(v3.y, s), quant1(v3.z, s), quant1(v3.w, s));
}

// ---------------- launch ----------------
extern "C" void kernel_launch(void* const* d_in, const int* in_sizes, int n_in,
                              void* d_out, int out_size) {
    (void)in_sizes; (void)n_in; (void)out_size;
    const int*   q_hidden = (const int*)d_in[0];
    const float* q_scale  = (const float*)d_in[1];
    const int*   w_qkv    = (const int*)d_in[3];
    const float* s_qkv    = (const float*)d_in[4];
    const int*   w_o      = (const int*)d_in[5];
    const float* s_o      = (const float*)d_in[6];
    float* out = (float*)d_out;

    int8_t *x8, *wq8, *wo8, *aq8;
    float *qkv, *attn, *ascale;
    cudaGetSymbolAddress((void**)&x8,     g_x8);
    cudaGetSymbolAddress((void**)&wq8,    g_wqkv8);
    cudaGetSymbolAddress((void**)&wo8,    g_wo8);
    cudaGetSymbolAddress((void**)&aq8,    g_attnq);
    cudaGetSymbolAddress((void**)&qkv,    g_qkv);
    cudaGetSymbolAddress((void**)&attn,   g_attn);
    cudaGetSymbolAddress((void**)&ascale, g_ascale);

    pack_int8_kernel<<<(T_*HID_/4 + 255) / 256, 256>>>(q_hidden, x8, T_*HID_/4);
    pack_int8_kernel<<<(OUTQKV_*HID_/4 + 255) / 256, 256>>>(w_qkv, wq8, OUTQKV_*HID_/4);
    pack_int8_kernel<<<(HID_*HID_/4 + 255) / 256, 256>>>(w_o, wo8, HID_*HID_/4);

    cudaFuncSetAttribute(gemm_s8_kernel, cudaFuncAttributeMaxDynamicSharedMemorySize, GSMEM2);
    gemm_s8_kernel<<<dim3(OUTQKV_/64, T_/128), 256, GSMEM2>>>(
        x8, wq8, s_qkv, q_scale, qkv, T_, OUTQKV_, HID_);

    rope_kernel<<<(T_*(H_+KV_)*64 + 255) / 256, 256>>>(qkv);

    const int attn_smem = ATTN_SMEM_FLOATS * sizeof(float);
    cudaFuncSetAttribute(attn_kernel, cudaFuncAttributeMaxDynamicSharedMemorySize, attn_smem);
    attn_kernel<<<dim3(S_/QB, H_, B_), 256, attn_smem>>>(qkv, attn);

    quant_kernel<<<T_, 256>>>(attn, aq8, ascale);

    gemm_s8_kernel<<<dim3(HID_/64, T_/128), 256, GSMEM2>>>(
        aq8, wo8, s_o, ascale, out, T_, HID_, HID_);
}

// round 12
// speedup vs baseline: 1.2657x; 1.0224x over previous
#include <cuda_runtime.h>
#include <cstdint>
#include <math.h>

#define B_ 2
#define S_ 2048
#define H_ 32
#define KV_ 8
#define D_ 128
#define T_ (B_*S_)                 // 4096
#define HID_ (H_*D_)               // 4096
#define OUTQKV_ ((H_+2*KV_)*D_)    // 6144

// ---------------- scratch (device globals; no allocation allowed) ----------------
__device__ int8_t g_x8[(size_t)T_*HID_];
__device__ int8_t g_wqkv8[(size_t)OUTQKV_*HID_];
__device__ int8_t g_wo8[(size_t)HID_*HID_];
__device__ float  g_qkv[(size_t)T_*OUTQKV_];
__device__ float  g_attn[(size_t)T_*HID_];
__device__ int8_t g_attnq[(size_t)T_*HID_];
__device__ float  g_ascale[T_];

// ---------------- f32x2 packed math helpers ----------------
#define FMA2(d,a,b) asm("fma.rn.f32x2 %0, %1, %2, %0;" : "+l"(d) : "l"(a), "l"(b))
#define MUL2(d,a,b) asm("mul.rn.f32x2 %0, %1, %2;" : "=l"(d) : "l"(a), "l"(b))

__device__ __forceinline__ unsigned long long pk2(float lo, float hi) {
    unsigned long long r;
    asm("mov.b64 %0, {%1,%2};" : "=l"(r) : "f"(lo), "f"(hi));
    return r;
}
__device__ __forceinline__ void upk2(float& lo, float& hi, unsigned long long v) {
    asm("mov.b64 {%0,%1}, %2;" : "=f"(lo), "=f"(hi) : "l"(v));
}

// ---------------- cp.async helpers ----------------
__device__ __forceinline__ void cp16(void* dst, const void* src) {
    unsigned d = (unsigned)__cvta_generic_to_shared(dst);
    asm volatile("cp.async.cg.shared.global [%0], [%1], 16;" :: "r"(d), "l"(src) : "memory");
}
__device__ __forceinline__ void cp4(void* dst, const void* src) {
    unsigned d = (unsigned)__cvta_generic_to_shared(dst);
    asm volatile("cp.async.ca.shared.global [%0], [%1], 4;" :: "r"(d), "l"(src) : "memory");
}
#define CP_COMMIT() asm volatile("cp.async.commit_group;" ::: "memory")
#define CP_WAIT(n)  asm volatile("cp.async.wait_group %0;" :: "n"(n) : "memory")

// ---------------- int32 -> int8 pack ----------------
__global__ void pack_int8_kernel(const int* __restrict__ in, int8_t* __restrict__ out, int n4) {
    int i = blockIdx.x * blockDim.x + threadIdx.x;
    if (i >= n4) return;
    int4 v = ((const int4*)in)[i];
    ((char4*)out)[i] = make_char4((signed char)v.x, (signed char)v.y,
                                  (signed char)v.z, (signed char)v.w);
}

// ---------------- block-scaled s8 GEMM (unchanged from R11: 88.7% tensor) ----------------
__device__ __forceinline__ void mma_s8(int c[4], const int a[4], const int b[2]) {
    asm volatile(
        "mma.sync.aligned.m16n8k32.row.col.s32.s8.s8.s32 "
        "{%0,%1,%2,%3}, {%4,%5,%6,%7}, {%8,%9}, {%0,%1,%2,%3};\n"
        : "+r"(c[0]), "+r"(c[1]), "+r"(c[2]), "+r"(c[3])
        : "r"(a[0]), "r"(a[1]), "r"(a[2]), "r"(a[3]), "r"(b[0]), "r"(b[1]));
}

#define GST2 27648                          // A(128*144) + B(64*144) per stage
#define GSMEM2 (2*GST2 + 2*64*4)            // + 2-stage col scales

__device__ __forceinline__ void gemm_load_stage(
    int8_t* dsm, const int8_t* A, const int8_t* Bm, const float* colscale,
    int bm0, int bn0, int K, int ng, int tid, int st, int grp)
{
    int8_t* sA = dsm + st * GST2;
    int8_t* sB = sA + 18432;
    float*  sS = (float*)(dsm + 2 * GST2) + st * 64;
    #pragma unroll
    for (int i = 0; i < 6; ++i) {
        int cidx = tid + i * 256;           // 0..1535: 1024 A chunks + 512 B chunks
        if (cidx < 1024) {
            int r = cidx >> 3, c = (cidx & 7) << 4;
            cp16(sA + r * 144 + c, A + (size_t)(bm0 + r) * K + (grp << 7) + c);
        } else {
            int j = cidx - 1024;
            int r = j >> 3, c = (j & 7) << 4;
            cp16(sB + r * 144 + c, Bm + (size_t)(bn0 + r) * K + (grp << 7) + c);
        }
    }
    if (tid < 64) cp4(sS + tid, colscale + (size_t)(bn0 + tid) * ng + grp);
}

__global__ __launch_bounds__(256, 2) void gemm_s8_kernel(
    const int8_t* __restrict__ A, const int8_t* __restrict__ Bm,
    const float* __restrict__ colscale, const float* __restrict__ rowscale,
    float* __restrict__ C, int M, int N, int K)
{
    extern __shared__ __align__(16) int8_t dsm[];

    const int tid  = threadIdx.x;
    const int warp = tid >> 5, lane = tid & 31;
    const int wm = warp & 3, wn = warp >> 2;
    const int g  = lane >> 2, tg = lane & 3;
    const int bm0 = blockIdx.y * 128, bn0 = blockIdx.x * 64;
    const int ng = K >> 7;

    float facc[2][4][4];
    #pragma unroll
    for (int mt = 0; mt < 2; ++mt)
        #pragma unroll
        for (int nt = 0; nt < 4; ++nt)
            #pragma unroll
            for (int e = 0; e < 4; ++e) facc[mt][nt][e] = 0.f;

    gemm_load_stage(dsm, A, Bm, colscale, bm0, bn0, K, ng, tid, 0, 0);
    CP_COMMIT();

    for (int grp = 0; grp < ng; ++grp) {
        const int st = grp & 1;
        if (grp + 1 < ng) {
            gemm_load_stage(dsm, A, Bm, colscale, bm0, bn0, K, ng, tid, st ^ 1, grp + 1);
            CP_COMMIT();
            CP_WAIT(1);
        } else {
            CP_WAIT(0);
        }
        __syncthreads();

        const int8_t* smA = dsm + st * GST2;
        const int8_t* smB = smA + 18432;
        const float*  sS  = (const float*)(dsm + 2 * GST2) + st * 64;

        int iacc[2][4][4];
        #pragma unroll
        for (int mt = 0; mt < 2; ++mt)
            #pragma unroll
            for (int nt = 0; nt < 4; ++nt)
                #pragma unroll
                for (int e = 0; e < 4; ++e) iacc[mt][nt][e] = 0;

        #pragma unroll
        for (int ks = 0; ks < 4; ++ks) {
            int a[2][4], b[4][2];
            #pragma unroll
            for (int mt = 0; mt < 2; ++mt) {
                const int8_t* p = smA + (wm * 32 + mt * 16 + g) * 144 + ks * 32 + tg * 4;
                a[mt][0] = *(const int*)(p);
                a[mt][1] = *(const int*)(p + 8 * 144);
                a[mt][2] = *(const int*)(p + 16);
                a[mt][3] = *(const int*)(p + 8 * 144 + 16);
            }
            #pragma unroll
            for (int nt = 0; nt < 4; ++nt) {
                const int8_t* p = smB + (wn * 32 + nt * 8 + g) * 144 + ks * 32 + tg * 4;
                b[nt][0] = *(const int*)(p);
                b[nt][1] = *(const int*)(p + 16);
            }
            #pragma unroll
            for (int mt = 0; mt < 2; ++mt)
                #pragma unroll
                for (int nt = 0; nt < 4; ++nt)
                    mma_s8(iacc[mt][nt], a[mt], b[nt]);
        }

        #pragma unroll
        for (int mt = 0; mt < 2; ++mt)
            #pragma unroll
            for (int nt = 0; nt < 4; ++nt) {
                int colb = wn * 32 + nt * 8 + tg * 2;
                float s0 = sS[colb], s1 = sS[colb + 1];
                facc[mt][nt][0] += (float)iacc[mt][nt][0] * s0;
                facc[mt][nt][1] += (float)iacc[mt][nt][1] * s1;
                facc[mt][nt][2] += (float)iacc[mt][nt][2] * s0;
                facc[mt][nt][3] += (float)iacc[mt][nt][3] * s1;
            }
        __syncthreads();
    }

    #pragma unroll
    for (int mt = 0; mt < 2; ++mt) {
        int r0 = bm0 + wm * 32 + mt * 16 + g;
        float rs0 = rowscale[r0], rs1 = rowscale[r0 + 8];
        #pragma unroll
        for (int nt = 0; nt < 4; ++nt) {
            int col = bn0 + wn * 32 + nt * 8 + tg * 2;
            *(float2*)(C + (size_t)r0 * N + col) =
                make_float2(facc[mt][nt][0] * rs0, facc[mt][nt][1] * rs0);
            *(float2*)(C + (size_t)(r0 + 8) * N + col) =
                make_float2(facc[mt][nt][2] * rs1, facc[mt][nt][3] * rs1);
        }
    }
}

// ---------------- RoPE (NeoX) in place ----------------
__global__ void rope_kernel(float* __restrict__ qkv) {
    int idx = blockIdx.x * 256 + threadIdx.x;
    if (idx >= T_ * (H_ + KV_) * 64) return;
    int i  = idx & 63;
    int hh = (idx >> 6) % (H_ + KV_);
    int t  = idx / ((H_ + KV_) * 64);
    int s  = t & (S_ - 1);
    int col = (hh < H_) ? hh * D_ : HID_ + (hh - H_) * D_;
    float inv = exp2f((float)i * -0.31143075889569023f);
    float ang = (float)s * inv;
    float sn, c;
    sincosf(ang, &sn, &c);
    float* p = qkv + (size_t)t * OUTQKV_ + col;
    float x1 = p[i], x2 = p[i + 64];
    p[i]      = x1 * c - x2 * sn;
    p[i + 64] = x2 * c + x1 * sn;
}

// ---------------- split-D f32x2 causal flash attention, cp.async double-buffered k/v ----------------
#define QB 128
#define KB 32
#define QPAD 68
#define SSTR (2*KB*QPAD)   // one k (or v) stage: [2 halves][KB][QPAD] = 4352 floats
// smem floats: q[2][QB][68] | k[2 stages][2][KB][68] | v[2 stages][2][KB][68] | part[QB][33] | alpha[QB]
#define ATTN_SMEM_FLOATS (2*QB*QPAD + 2*SSTR + 2*SSTR + QB*33 + QB)

__global__ __launch_bounds__(256, 1) void attn_kernel(const float* __restrict__ qkv,
                                                      float* __restrict__ attn) {
    extern __shared__ float sm[];
    float* q_s     = sm;
    float* k_s     = q_s + 2 * QB * QPAD;     // [st][half][KB][QPAD]
    float* v_s     = k_s + 2 * SSTR;
    float* part    = v_s + 2 * SSTR;          // [QB][33]
    float* alpha_s = part + QB * 33;

    const int tid = threadIdx.x;
    const int warp = tid >> 5, lane = tid & 31;
    const int half = warp >> 2;
    const int q = ((warp & 3) << 5) | lane;
    const int qb = (gridDim.x - 1) - blockIdx.x;   // heaviest blocks first
    const int h = blockIdx.y, b = blockIdx.z;
    const int g = h >> 2;
    const int q0 = qb * QB;
    const int qpos = q0 + q;
    const float scale = 0.08838834764831845f;
    const int nkb = (q0 + QB) / KB;

    // prefetch k/v tile 0 into stage 0 (cp.async)
    {
        const int st = 0, kb = 0;
        for (int i = tid; i < KB * 32 * 2; i += 256) {
            int arr = i >> 10, rem = i & 1023;
            int r = rem >> 5, c = rem & 31;
            int hh = c >> 4, cc = c & 15;
            const float* src = qkv + (size_t)(b * S_ + kb * KB + r) * OUTQKV_
                             + HID_ + arr * (KV_ * D_) + g * D_ + c * 4;
            float* dst = (arr ? v_s : k_s) + st * SSTR + hh * (KB * QPAD) + r * QPAD + cc * 4;
            cp16(dst, src);
        }
        CP_COMMIT();
    }

    // load q block (scale-premultiplied), split by dim-half
    for (int i = tid; i < QB * 32; i += 256) {
        int r = i >> 5, c = i & 31;
        int hh = c >> 4, cc = c & 15;
        float4 v = *(const float4*)(qkv + (size_t)(b * S_ + q0 + r) * OUTQKV_ + h * D_ + c * 4);
        v.x *= scale; v.y *= scale; v.z *= scale; v.w *= scale;
        *(float4*)(q_s + hh * (QB * QPAD) + r * QPAD + cc * 4) = v;
    }

    unsigned long long o2[32];
    #pragma unroll
    for (int i = 0; i < 32; ++i) o2[i] = 0ull;
    float m = -1e30f, l = 0.f;

    const float* qrow = q_s + half * (QB * QPAD) + q * QPAD;

    for (int kb = 0; kb < nkb; ++kb) {
        const int st = kb & 1;
        CP_WAIT(0);
        __syncthreads();   // stage st visible to all; stage st^1 fully consumed (prev iter done)

        if (kb + 1 < nkb) {   // prefetch next tile into st^1 during compute
            for (int i = tid; i < KB * 32 * 2; i += 256) {
                int arr = i >> 10, rem = i & 1023;
                int r = rem >> 5, c = rem & 31;
                int hh = c >> 4, cc = c & 15;
                const float* src = qkv + (size_t)(b * S_ + (kb + 1) * KB + r) * OUTQKV_
                                 + HID_ + arr * (KV_ * D_) + g * D_ + c * 4;
                float* dst = (arr ? v_s : k_s) + (st ^ 1) * SSTR + hh * (KB * QPAD) + r * QPAD + cc * 4;
                cp16(dst, src);
            }
        }
        CP_COMMIT();

        const float* kh = k_s + st * SSTR + half * (KB * QPAD);
        const float* vh = v_s + st * SSTR + half * (KB * QPAD);

        // ---- QK over this thread's 64 dims ----
        unsigned long long s2[32];
        #pragma unroll
        for (int j = 0; j < 32; ++j) s2[j] = 0ull;
        for (int dg = 0; dg < 16; ++dg) {
            double2 qd = *(const double2*)(qrow + dg * 4);
            unsigned long long q01 = __double_as_longlong(qd.x);
            unsigned long long q23 = __double_as_longlong(qd.y);
            #pragma unroll
            for (int j = 0; j < 32; ++j) {
                double2 kd = *(const double2*)(kh + j * QPAD + dg * 4);
                FMA2(s2[j], q01, __double_as_longlong(kd.x));
                FMA2(s2[j], q23, __double_as_longlong(kd.y));
            }
        }
        float s[32];
        #pragma unroll
        for (int j = 0; j < 32; ++j) { float lo, hi; upk2(lo, hi, s2[j]); s[j] = lo + hi; }

        // ---- cross-half reduction + softmax (half 0 owns state) ----
        if (half == 1) {
            #pragma unroll
            for (int j = 0; j < 32; ++j) part[q * 33 + j] = s[j];
        }
        __syncthreads();
        float alpha = 0.f;
        if (half == 0) {
            const int kbase = kb * KB;
            #pragma unroll
            for (int j = 0; j < 32; ++j) {
                float t = s[j] + part[q * 33 + j];
                s[j] = (kbase + j > qpos) ? -1e30f : t;
            }
            float mn = m;
            #pragma unroll
            for (int j = 0; j < 32; ++j) mn = fmaxf(mn, s[j]);
            alpha = __expf(m - mn);
            m = mn;
            float ps = 0.f;
            #pragma unroll
            for (int j = 0; j < 32; ++j) { s[j] = __expf(s[j] - mn); ps += s[j]; }
            l = l * alpha + ps;
            #pragma unroll
            for (int j = 0; j < 32; ++j) part[q * 33 + j] = s[j];
            alpha_s[q] = alpha;
        }
        __syncthreads();
        if (half == 1) alpha = alpha_s[q];

        // ---- rescale + PV over this thread's 64 dims ----
        unsigned long long a2 = pk2(alpha, alpha);
        #pragma unroll
        for (int i = 0; i < 32; ++i) MUL2(o2[i], o2[i], a2);

        for (int j = 0; j < 32; ++j) {
            float pj = part[q * 33 + j];
            unsigned long long p2 = pk2(pj, pj);
            const float* vr = vh + j * QPAD;
            #pragma unroll
            for (int dg = 0; dg < 16; ++dg) {
                double2 vd = *(const double2*)(vr + dg * 4);
                FMA2(o2[2 * dg],     p2, __double_as_longlong(vd.x));
                FMA2(o2[2 * dg + 1], p2, __double_as_longlong(vd.y));
            }
        }
    }

    if (half == 0) alpha_s[q] = 1.0f / l;
    __syncthreads();
    float invl = alpha_s[q];
    float* op = attn + (size_t)(b * S_ + qpos) * HID_ + h * D_ + half * 64;
    #pragma unroll
    for (int i = 0; i < 32; ++i) {
        float lo, hi; upk2(lo, hi, o2[i]);
        *(float2*)(op + i * 2) = make_float2(lo * invl, hi * invl);
    }
}

// ---------------- per-token amax quantization ----------------
__device__ __forceinline__ signed char quant1(float x, float s) {
    float r = rintf(x / s);
    r = fminf(fmaxf(r, -127.f), 127.f);
    return (signed char)(int)r;
}

__global__ __launch_bounds__(256) void quant_kernel(const float* __restrict__ attn,
                                                    int8_t* __restrict__ q8,
                                                    float* __restrict__ ascale) {
    const int t = blockIdx.x, tid = threadIdx.x;
    const float4* row = (const float4*)(attn + (size_t)t * HID_);
    float4 v0 = row[tid], v1 = row[tid + 256], v2 = row[tid + 512], v3 = row[tid + 768];
    float mx = 0.f;
    mx = fmaxf(mx, fmaxf(fmaxf(fabsf(v0.x), fabsf(v0.y)), fmaxf(fabsf(v0.z), fabsf(v0.w))));
    mx = fmaxf(mx, fmaxf(fmaxf(fabsf(v1.x), fabsf(v1.y)), fmaxf(fabsf(v1.z), fabsf(v1.w))));
    mx = fmaxf(mx, fmaxf(fmaxf(fabsf(v2.x), fabsf(v2.y)), fmaxf(fabsf(v2.z), fabsf(v2.w))));
    mx = fmaxf(mx, fmaxf(fmaxf(fabsf(v3.x), fabsf(v3.y)), fmaxf(fabsf(v3.z), fabsf(v3.w))));
    #pragma unroll
    for (int off = 16; off; off >>= 1) mx = fmaxf(mx, __shfl_xor_sync(0xffffffffu, mx, off));
    __shared__ float red[8];
    if ((tid & 31) == 0) red[tid >> 5] = mx;
    __syncthreads();
    if (tid == 0) {
        float mm = red[0];
        #pragma unroll
        for (int i = 1; i < 8; ++i) mm = fmaxf(mm, red[i]);
        red[0] = fmaxf(mm, 1e-6f);
    }
    __syncthreads();
    float s = red[0] / 127.0f;
    if (tid == 0) ascale[t] = s;
    char4* outp = (char4*)(q8 + (size_t)t * HID_);
    outp[tid]       = make_char4(quant1(v0.x, s), quant1(v0.y, s), quant1(v0.z, s), quant1(v0.w, s));
    outp[tid + 256] = make_char4(quant1(v1.x, s), quant1(v1.y, s), quant1(v1.z, s), quant1(v1.w, s));
    outp[tid + 512] = make_char4(quant1(v2.x, s), quant1(v2.y, s), quant1(v2.z, s), quant1(v2.w, s));
    outp[tid + 768] = make_char4(quant1(v3.x, s), quant1(v3.y, s), quant1(v3.z, s), quant1(v3.w, s));
}

// ---------------- launch ----------------
extern "C" void kernel_launch(void* const* d_in, const int* in_sizes, int n_in,
                              void* d_out, int out_size) {
    (void)in_sizes; (void)n_in; (void)out_size;
    const int*   q_hidden = (const int*)d_in[0];
    const float* q_scale  = (const float*)d_in[1];
    const int*   w_qkv    = (const int*)d_in[3];
    const float* s_qkv    = (const float*)d_in[4];
    const int*   w_o      = (const int*)d_in[5];
    const float* s_o      = (const float*)d_in[6];
    float* out = (float*)d_out;

    int8_t *x8, *wq8, *wo8, *aq8;
    float *qkv, *attn, *ascale;
    cudaGetSymbolAddress((void**)&x8,     g_x8);
    cudaGetSymbolAddress((void**)&wq8,    g_wqkv8);
    cudaGetSymbolAddress((void**)&wo8,    g_wo8);
    cudaGetSymbolAddress((void**)&aq8,    g_attnq);
    cudaGetSymbolAddress((void**)&qkv,    g_qkv);
    cudaGetSymbolAddress((void**)&attn,   g_attn);
    cudaGetSymbolAddress((void**)&ascale, g_ascale);

    pack_int8_kernel<<<(T_*HID_/4 + 255) / 256, 256>>>(q_hidden, x8, T_*HID_/4);
    pack_int8_kernel<<<(OUTQKV_*HID_/4 + 255) / 256, 256>>>(w_qkv, wq8, OUTQKV_*HID_/4);
    pack_int8_kernel<<<(HID_*HID_/4 + 255) / 256, 256>>>(w_o, wo8, HID_*HID_/4);

    cudaFuncSetAttribute(gemm_s8_kernel, cudaFuncAttributeMaxDynamicSharedMemorySize, GSMEM2);
    gemm_s8_kernel<<<dim3(OUTQKV_/64, T_/128), 256, GSMEM2>>>(
        x8, wq8, s_qkv, q_scale, qkv, T_, OUTQKV_, HID_);

    rope_kernel<<<(T_*(H_+KV_)*64 + 255) / 256, 256>>>(qkv);

    const int attn_smem = ATTN_SMEM_FLOATS * sizeof(float);  // 156672 B
    cudaFuncSetAttribute(attn_kernel, cudaFuncAttributeMaxDynamicSharedMemorySize, attn_smem);
    attn_kernel<<<dim3(S_/QB, H_, B_), 256, attn_smem>>>(qkv, attn);

    quant_kernel<<<T_, 256>>>(attn, aq8, ascale);

    gemm_s8_kernel<<<dim3(HID_/64, T_/128), 256, GSMEM2>>>(
        aq8, wo8, s_o, ascale, out, T_, HID_, HID_);
}